// round 11
// baseline (speedup 1.0000x reference)
#include <cuda_runtime.h>
#include <cuda_bf16.h>
#include <cstdint>

#define NN 50000
#define NR 32
#define DD 64
#define NE_MAX 1600000
#define TILE 128
#define PADMAX (NR * TILE)
#define SA  72    // As stride (u32): k-paired LDS.64 frags conflict-free
#define SWP 132   // Wp stride (u32): LDS.128 B frags conflict-free
#define WP_ROW (32 * SWP)   // 4224 u32 per relation
#define ESTR 72   // epilogue stride

// Packed relation-sorted edges: (src, dst, norm_bits, 0)
__device__ int4     g_edge[NE_MAX + PADMAX];
__device__ int      g_binCount[NR];
__device__ int      g_cursor[NR];
__device__ int      g_tileRel[NE_MAX / TILE + NR + 2];
__device__ int      g_numTiles;
// Precomputed tf32 operands (rounded once, fragment-ready layouts)
__device__ uint32_t g_hT[(size_t)NN * DD];
__device__ uint32_t g_Wp[(size_t)NR * WP_ROW];

__device__ __forceinline__ uint32_t f2tf32(float f) {
    uint32_t r;
    asm("cvt.rna.tf32.f32 %0, %1;" : "=r"(r) : "f"(f));
    return r;
}
__device__ __forceinline__ void mma_tf32(float* c, const uint32_t* a, const uint32_t* b) {
    asm volatile(
        "mma.sync.aligned.m16n8k8.row.col.f32.tf32.tf32.f32 "
        "{%0,%1,%2,%3}, {%4,%5,%6,%7}, {%8,%9}, {%0,%1,%2,%3};"
        : "+f"(c[0]), "+f"(c[1]), "+f"(c[2]), "+f"(c[3])
        : "r"(a[0]), "r"(a[1]), "r"(a[2]), "r"(a[3]), "r"(b[0]), "r"(b[1]));
}
__device__ __forceinline__ uint32_t smem_u32(const void* p) {
    uint32_t a;
    asm("{ .reg .u64 t; cvta.to.shared.u64 t, %1; cvt.u32.u64 %0, t; }" : "=r"(a) : "l"(p));
    return a;
}
__device__ __forceinline__ void cp16(uint32_t saddr, const void* gaddr) {
    asm volatile("cp.async.ca.shared.global [%0], [%1], 16;"
                 :: "r"(saddr), "l"(gaddr) : "memory");
}
#define CP_COMMIT() asm volatile("cp.async.commit_group;" ::: "memory")
#define CP_WAIT0()  asm volatile("cp.async.wait_group 0;" ::: "memory")

// ---------------------------------------------------------------------------
__global__ void k_hist(const int* __restrict__ rel, int n) {
    __shared__ int sh[NR];
    if (threadIdx.x < NR) sh[threadIdx.x] = 0;
    __syncthreads();
    for (int i = blockIdx.x * blockDim.x + threadIdx.x; i < n;
         i += gridDim.x * blockDim.x)
        atomicAdd(&sh[__ldg(rel + i)], 1);
    __syncthreads();
    if (threadIdx.x < NR) atomicAdd(&g_binCount[threadIdx.x], sh[threadIdx.x]);
}

__global__ void k_prefix() {   // 32 threads
    int r = threadIdx.x;
    int cnt = g_binCount[r];
    int tiles = (cnt + TILE - 1) / TILE;
    int t = tiles;
#pragma unroll
    for (int d = 1; d < 32; d <<= 1) {
        int v = __shfl_up_sync(0xFFFFFFFFu, t, d);
        if (r >= d) t += v;
    }
    int tileBase = t - tiles;
    int base = tileBase * TILE;
    g_cursor[r] = base;
    for (int i = 0; i < tiles; i++) g_tileRel[tileBase + i] = r;
    for (int i = base + cnt; i < base + tiles * TILE; i++)
        g_edge[i] = make_int4(0, 0, 0, 0);
    if (r == 31) g_numTiles = t;
}

// ---------------------------------------------------------------------------
// Scatter with block-local ordering: records leave in output order, so global
// stores form contiguous per-relation runs (~full 128B lines, not 32B sectors).
// ---------------------------------------------------------------------------
__global__ void __launch_bounds__(256) k_scatter(const int* __restrict__ src,
                                                 const int* __restrict__ dst,
                                                 const int* __restrict__ rel,
                                                 const float* __restrict__ norm,
                                                 int n) {
    __shared__ int4 buf[256];
    __shared__ int sh_pos[NR], sh_pref[NR], sh_delta[NR];
    const int tid = threadIdx.x;
    if (tid < NR) sh_pos[tid] = 0;
    __syncthreads();

    const int i = blockIdx.x * 256 + tid;
    const bool ok = i < n;
    int r = 0, s = 0, d = 0, rank = 0;
    float nm = 0.0f;
    if (ok) {
        r = __ldg(rel + i); s = __ldg(src + i);
        d = __ldg(dst + i); nm = __ldg(norm + i);
        rank = atomicAdd(&sh_pos[r], 1);
    }
    __syncthreads();

    if (tid < NR) {
        int cnt = sh_pos[tid];
        int t = cnt;
#pragma unroll
        for (int dd = 1; dd < 32; dd <<= 1) {
            int v = __shfl_up_sync(0xFFFFFFFFu, t, dd);
            if (tid >= dd) t += v;
        }
        int pref = t - cnt;                    // block-local exclusive scan
        sh_pref[tid] = pref;
        int base = (cnt > 0) ? atomicAdd(&g_cursor[tid], cnt) : 0;
        sh_delta[tid] = base - pref;
    }
    __syncthreads();

    if (ok) buf[sh_pref[r] + rank] = make_int4(s, d, __float_as_int(nm), r);
    __syncthreads();

    const int total = min(256, n - blockIdx.x * 256);
    if (tid < total) {
        int4 rec = buf[tid];
        const int pos = sh_delta[rec.w] + tid;
        rec.w = 0;
        g_edge[pos] = rec;
    }
}

// ---------------------------------------------------------------------------
// Convert h and W to tf32 fragment-ready layouts (rounded once).
// ---------------------------------------------------------------------------
__global__ void __launch_bounds__(256) k_convert(const float* __restrict__ h,
                                                 const float* __restrict__ W) {
    const int i = blockIdx.x * 256 + threadIdx.x;
    if (i < NN * DD) {
        const int n = i >> 6, k = i & 63;
        const int slot = (k >> 3) * 8 + (k & 3) * 2 + ((k >> 2) & 1);
        g_hT[(n << 6) + slot] = f2tf32(__ldg(h + i));
    }
    if (i < NR * DD * DD) {
        const int r = i >> 12, rem = i & 4095, k = rem >> 6, o = rem & 63;
        const int kp = (k >> 3) * 4 + (k & 3), half = (k >> 2) & 1;
        const int col = (o & 7) * 8 + (o >> 3);
        g_Wp[(size_t)r * WP_ROW + kp * SWP + col * 2 + half] = f2tf32(__ldg(W + i));
    }
}

// ---------------------------------------------------------------------------
// Fused kernel: 256 threads (8 warps) per 128-edge tile. Warp = 32 rows x
// 32 outs (N-split: nhalf = wid&1). cp.async stage, mma.sync tf32, coalesced
// red.v4 epilogue via smem transpose.
// Smem u32: Wp[4224] | As[9216] | dst[128] | norm[128] | src[128] = 55.3 KB
// __launch_bounds__(256,3): <=85 regs, 3 blocks/SM = 24 warps/SM.
// ---------------------------------------------------------------------------
__global__ void __launch_bounds__(256, 3) rgcn_fused(float* __restrict__ out) {
    extern __shared__ uint32_t smem[];
    uint32_t* Wp     = smem;                       // 4224
    uint32_t* As     = smem + WP_ROW;              // 9216
    int*      s_dst  = (int*)(As + TILE * SA);     // 128
    float*    s_norm = (float*)(s_dst + TILE);     // 128
    int*      s_src  = (int*)(s_norm + TILE);      // 128
    float*    E      = (float*)smem;               // epilogue overlay (128x72)

    const int tile = blockIdx.x;
    if (tile >= g_numTiles) return;
    const int r    = g_tileRel[tile];
    const int row0 = tile << 7;

    const int tid = threadIdx.x, wid = tid >> 5, lane = tid & 31;
    const int g = lane >> 2, tg = lane & 3;
    const int wrow  = (wid >> 1) * 32;   // row group
    const int nhalf = wid & 1;           // N half: nt 4*nhalf .. 4*nhalf+3

    if (tid < TILE) {   // meta (coalesced LDG.128) -> smem
        const int4 e = g_edge[row0 + tid];
        s_src[tid]  = e.x;
        s_dst[tid]  = e.y;
        s_norm[tid] = __int_as_float(e.z);
    }
    // Stage W fragment-image: 1056 x 16B chunks.
    {
        const uint32_t* wg = g_Wp + (size_t)r * WP_ROW;
        const uint32_t wsm = smem_u32(Wp);
#pragma unroll
        for (int j = 0; j < 5; j++) {
            const int idx = j * 256 + tid;
            if (idx < 1056) cp16(wsm + idx * 16, wg + idx * 4);
        }
    }
    __syncthreads();    // s_src visible before A-stage addresses

    // Stage A: gather 128 h-rows (k-paired tf32), 16 threads/row x 16B.
    {
        const int arow = tid >> 4, c = tid & 15;
        const uint32_t asm_base = smem_u32(As);
#pragma unroll
        for (int p = 0; p < 8; p++) {
            const int row = p * 16 + arow;
            cp16(asm_base + (row * SA + c * 4) * 4,
                 g_hT + ((size_t)s_src[row] << 6) + c * 4);
        }
    }
    CP_COMMIT();
    CP_WAIT0();
    __syncthreads();

    // Mainloop: warp tile 32 x 32 (2 mt x 4 nt).
    float acc[2][4][4];
#pragma unroll
    for (int mt = 0; mt < 2; mt++)
#pragma unroll
        for (int nt = 0; nt < 4; nt++)
#pragma unroll
            for (int q = 0; q < 4; q++) acc[mt][nt][q] = 0.0f;

#pragma unroll
    for (int ks = 0; ks < 8; ks++) {
        uint32_t a[2][4];
#pragma unroll
        for (int mt = 0; mt < 2; mt++) {
            const int r0 = wrow + mt * 16 + g;
            const uint2 p0 = *(const uint2*)&As[r0 * SA + ks * 8 + tg * 2];
            const uint2 p1 = *(const uint2*)&As[(r0 + 8) * SA + ks * 8 + tg * 2];
            a[mt][0] = p0.x; a[mt][1] = p1.x; a[mt][2] = p0.y; a[mt][3] = p1.y;
        }
        uint32_t b[4][2];
        const uint32_t* brow = &Wp[(ks * 4 + tg) * SWP + g * 16];
#pragma unroll
        for (int m = 0; m < 2; m++) {
            const uint4 bb = *(const uint4*)(brow + (2 * nhalf + m) * 4);
            b[2 * m][0]     = bb.x; b[2 * m][1]     = bb.y;
            b[2 * m + 1][0] = bb.z; b[2 * m + 1][1] = bb.w;
        }
#pragma unroll
        for (int mt = 0; mt < 2; mt++)
#pragma unroll
            for (int nt = 0; nt < 4; nt++)
                mma_tf32(acc[mt][nt], a[mt], b[nt]);
    }

    // Epilogue: norm-scale into smem (conflict-free STS.64), coalesced red.v4.
    __syncthreads();
#pragma unroll
    for (int mt = 0; mt < 2; mt++) {
        const int lr0 = wrow + mt * 16 + g, lr1 = lr0 + 8;
        const float n0 = s_norm[lr0], n1 = s_norm[lr1];
#pragma unroll
        for (int nt = 0; nt < 4; nt++) {
            const int oc = (nhalf * 4 + nt) * 8 + 2 * tg;
            *(float2*)&E[lr0 * ESTR + oc] =
                make_float2(acc[mt][nt][0] * n0, acc[mt][nt][1] * n0);
            *(float2*)&E[lr1 * ESTR + oc] =
                make_float2(acc[mt][nt][2] * n1, acc[mt][nt][3] * n1);
        }
    }
    __syncthreads();

    const int erow = tid >> 4, q4 = (tid & 15) * 4;
#pragma unroll
    for (int p = 0; p < 8; p++) {
        const int row = p * 16 + erow;
        const float4 v = *(const float4*)&E[row * ESTR + q4];
        float* o = out + (size_t)s_dst[row] * DD + q4;
        asm volatile("red.global.add.v4.f32 [%0], {%1, %2, %3, %4};"
                     :: "l"(o), "f"(v.x), "f"(v.y), "f"(v.z), "f"(v.w)
                     : "memory");
    }
}

// ---------------------------------------------------------------------------
extern "C" void kernel_launch(void* const* d_in, const int* in_sizes, int n_in,
                              void* d_out, int out_size) {
    const float* h    = (const float*)d_in[0];
    const float* W    = (const float*)d_in[1];
    const int*   src  = (const int*)d_in[2];
    const int*   dst  = (const int*)d_in[3];
    const int*   rel  = (const int*)d_in[4];
    const float* norm = (const float*)d_in[5];
    float*       out  = (float*)d_out;

    const int n_edges = in_sizes[2];   // 1600000

    void* p_cnt;
    cudaGetSymbolAddress(&p_cnt, g_binCount);
    cudaMemsetAsync(out,   0, (size_t)out_size * sizeof(float), 0);
    cudaMemsetAsync(p_cnt, 0, sizeof(int) * NR, 0);

    k_convert<<<(NN * DD + 255) / 256, 256>>>(h, W);
    k_hist<<<592, 256>>>(rel, n_edges);
    k_prefix<<<1, 32>>>();
    k_scatter<<<(n_edges + 255) / 256, 256>>>(src, dst, rel, norm, n_edges);

    const int smem_bytes = (WP_ROW + TILE * SA + 3 * TILE) * 4;
    static bool attr_set = false;
    if (!attr_set) {
        cudaFuncSetAttribute(rgcn_fused,
                             cudaFuncAttributeMaxDynamicSharedMemorySize,
                             smem_bytes);
        attr_set = true;
    }
    const int max_tiles = n_edges / TILE + NR + 1;
    rgcn_fused<<<max_tiles, 256, smem_bytes>>>(out);
}

// round 12
// speedup vs baseline: 1.0610x; 1.0610x over previous
#include <cuda_runtime.h>
#include <cuda_bf16.h>
#include <cstdint>

#define NN 50000
#define NR 32
#define DD 64
#define NE_MAX 1600000
#define TILE 128
#define PADMAX (NR * TILE)
#define SA  72    // As stride (u32): k-paired LDS.64 frags conflict-free
#define SWP 132   // Wp stride (u32): LDS.128 B frags conflict-free
#define WP_ROW (32 * SWP)   // 4224 u32 per relation
#define ESTR 72   // epilogue stride

// Packed relation-sorted edges: (src, dst, norm_bits, 0)
__device__ int4     g_edge[NE_MAX + PADMAX];
__device__ int      g_binCount[NR];
__device__ int      g_cursor[NR];
__device__ int      g_tileRel[NE_MAX / TILE + NR + 2];
__device__ int      g_numTiles;
// Precomputed tf32 operands (rounded once, fragment-ready layouts)
__device__ uint32_t g_hT[(size_t)NN * DD];
__device__ uint32_t g_Wp[(size_t)NR * WP_ROW];

__device__ __forceinline__ uint32_t f2tf32(float f) {
    uint32_t r;
    asm("cvt.rna.tf32.f32 %0, %1;" : "=r"(r) : "f"(f));
    return r;
}
__device__ __forceinline__ void mma_tf32(float* c, const uint32_t* a, const uint32_t* b) {
    asm volatile(
        "mma.sync.aligned.m16n8k8.row.col.f32.tf32.tf32.f32 "
        "{%0,%1,%2,%3}, {%4,%5,%6,%7}, {%8,%9}, {%0,%1,%2,%3};"
        : "+f"(c[0]), "+f"(c[1]), "+f"(c[2]), "+f"(c[3])
        : "r"(a[0]), "r"(a[1]), "r"(a[2]), "r"(a[3]), "r"(b[0]), "r"(b[1]));
}
__device__ __forceinline__ uint32_t smem_u32(const void* p) {
    uint32_t a;
    asm("{ .reg .u64 t; cvta.to.shared.u64 t, %1; cvt.u32.u64 %0, t; }" : "=r"(a) : "l"(p));
    return a;
}
__device__ __forceinline__ void cp16(uint32_t saddr, const void* gaddr) {
    asm volatile("cp.async.ca.shared.global [%0], [%1], 16;"
                 :: "r"(saddr), "l"(gaddr) : "memory");
}
#define CP_COMMIT() asm volatile("cp.async.commit_group;" ::: "memory")
#define CP_WAIT0()  asm volatile("cp.async.wait_group 0;" ::: "memory")

// ---------------------------------------------------------------------------
// Preamble A: convert h and W to tf32 fragment-ready layouts (rounded once)
// AND accumulate the per-relation edge histogram (merged: hist's 6.4MB read
// hides under convert's memory traffic; one fewer kernel launch).
// ---------------------------------------------------------------------------
__global__ void __launch_bounds__(256) k_convert_hist(const float* __restrict__ h,
                                                      const float* __restrict__ W,
                                                      const int* __restrict__ rel,
                                                      int n_edges) {
    __shared__ int sh[NR];
    if (threadIdx.x < NR) sh[threadIdx.x] = 0;
    __syncthreads();

    const int i = blockIdx.x * 256 + threadIdx.x;
    if (i < NN * DD) {
        const int n = i >> 6, k = i & 63;
        const int slot = (k >> 3) * 8 + (k & 3) * 2 + ((k >> 2) & 1);
        g_hT[(n << 6) + slot] = f2tf32(__ldg(h + i));
    }
    if (i < NR * DD * DD) {
        const int r = i >> 12, rem = i & 4095, k = rem >> 6, o = rem & 63;
        const int kp = (k >> 3) * 4 + (k & 3), half = (k >> 2) & 1;
        const int col = (o & 7) * 8 + (o >> 3);
        g_Wp[(size_t)r * WP_ROW + kp * SWP + col * 2 + half] = f2tf32(__ldg(W + i));
    }
    if (i < n_edges) atomicAdd(&sh[__ldg(rel + i)], 1);
    __syncthreads();
    if (threadIdx.x < NR && sh[threadIdx.x] > 0)
        atomicAdd(&g_binCount[threadIdx.x], sh[threadIdx.x]);
}

// ---------------------------------------------------------------------------
// Preamble B: TILE-aligned prefix, tile->rel map, pad zeroing. 32 threads.
// ---------------------------------------------------------------------------
__global__ void k_prefix() {
    int r = threadIdx.x;
    int cnt = g_binCount[r];
    int tiles = (cnt + TILE - 1) / TILE;
    int t = tiles;
#pragma unroll
    for (int d = 1; d < 32; d <<= 1) {
        int v = __shfl_up_sync(0xFFFFFFFFu, t, d);
        if (r >= d) t += v;
    }
    int tileBase = t - tiles;
    int base = tileBase * TILE;
    g_cursor[r] = base;
    for (int i = 0; i < tiles; i++) g_tileRel[tileBase + i] = r;
    for (int i = base + cnt; i < base + tiles * TILE; i++)
        g_edge[i] = make_int4(0, 0, 0, 0);
    if (r == 31) g_numTiles = t;
}

// ---------------------------------------------------------------------------
// Preamble C: scatter, 2 edges per thread (barriers amortized over 512 edges).
// ---------------------------------------------------------------------------
__global__ void __launch_bounds__(256) k_scatter(const int* __restrict__ src,
                                                 const int* __restrict__ dst,
                                                 const int* __restrict__ rel,
                                                 const float* __restrict__ norm,
                                                 int n) {
    __shared__ int sh_cnt[NR], sh_base[NR];
    const int tid = threadIdx.x;
    if (tid < NR) sh_cnt[tid] = 0;
    __syncthreads();

    const int i0 = blockIdx.x * 512 + tid;
    const int i1 = i0 + 256;
    const bool ok0 = i0 < n, ok1 = i1 < n;
    int r0 = 0, r1 = 0, rank0 = 0, rank1 = 0;
    int4 e0, e1;
    if (ok0) {
        r0 = __ldg(rel + i0);
        e0 = make_int4(__ldg(src + i0), __ldg(dst + i0),
                       __float_as_int(__ldg(norm + i0)), 0);
        rank0 = atomicAdd(&sh_cnt[r0], 1);
    }
    if (ok1) {
        r1 = __ldg(rel + i1);
        e1 = make_int4(__ldg(src + i1), __ldg(dst + i1),
                       __float_as_int(__ldg(norm + i1)), 0);
        rank1 = atomicAdd(&sh_cnt[r1], 1);
    }
    __syncthreads();
    if (tid < NR && sh_cnt[tid] > 0)
        sh_base[tid] = atomicAdd(&g_cursor[tid], sh_cnt[tid]);
    __syncthreads();
    if (ok0) g_edge[sh_base[r0] + rank0] = e0;
    if (ok1) g_edge[sh_base[r1] + rank1] = e1;
}

// ---------------------------------------------------------------------------
// Fused kernel (R10 verbatim): one 128-edge tile per block.
//   cp.async stage (W fragment-image + gathered h rows) -> mma.sync tf32
//   (LDS.64 A frags, LDS.128 B frags) -> smem-transposed coalesced red.v4.
// Smem u32: Wp[4224] | As[9216] | dst[128] | norm[128] = 53.5 KB -> 4 blk/SM.
// ---------------------------------------------------------------------------
__global__ void __launch_bounds__(128) rgcn_fused(float* __restrict__ out) {
    extern __shared__ uint32_t smem[];
    uint32_t* Wp     = smem;                       // 4224
    uint32_t* As     = smem + WP_ROW;              // 9216
    int*      s_dst  = (int*)(As + TILE * SA);     // 128
    float*    s_norm = (float*)(s_dst + TILE);     // 128
    float*    E      = (float*)smem;               // epilogue overlay

    const int tile = blockIdx.x;
    if (tile >= g_numTiles) return;
    const int r    = g_tileRel[tile];
    const int row0 = tile << 7;

    const int tid = threadIdx.x, wid = tid >> 5, lane = tid & 31;
    const int g = lane >> 2, tg = lane & 3;

    {   // meta: one packed record per thread (coalesced LDG.128)
        const int4 e = g_edge[row0 + tid];
        s_dst[tid]  = e.y;
        s_norm[tid] = __int_as_float(e.z);
    }

    // Stage W fragment-image: 4224 u32 = 1056 x 16B chunks.
    {
        const uint32_t* wg = g_Wp + (size_t)r * WP_ROW;
        const uint32_t wsm = smem_u32(Wp);
#pragma unroll
        for (int j = 0; j < 9; j++) {
            const int idx = j * 128 + tid;
            if (idx < 1056) cp16(wsm + idx * 16, wg + idx * 4);
        }
    }
    // Stage A: gather 128 h-rows (k-paired tf32), 16 threads/row x 16B.
    {
        const int arow = tid >> 4, c = tid & 15;
        const uint32_t asm_base = smem_u32(As);
#pragma unroll
        for (int p = 0; p < 16; p++) {
            const int row = p * 8 + arow;
            const int s = ((const int*)g_edge)[(size_t)(row0 + row) * 4];  // .x
            cp16(asm_base + (row * SA + c * 4) * 4,
                 g_hT + ((size_t)s << 6) + c * 4);
        }
    }
    CP_COMMIT();
    CP_WAIT0();
    __syncthreads();

    // Mainloop: warp tile 32 x 64.
    float acc[2][8][4];
#pragma unroll
    for (int mt = 0; mt < 2; mt++)
#pragma unroll
        for (int nt = 0; nt < 8; nt++)
#pragma unroll
            for (int q = 0; q < 4; q++) acc[mt][nt][q] = 0.0f;

    const int wrow = wid * 32;
#pragma unroll
    for (int ks = 0; ks < 8; ks++) {
        uint32_t a[2][4];
#pragma unroll
        for (int mt = 0; mt < 2; mt++) {
            const int r0 = wrow + mt * 16 + g;
            const uint2 p0 = *(const uint2*)&As[r0 * SA + ks * 8 + tg * 2];
            const uint2 p1 = *(const uint2*)&As[(r0 + 8) * SA + ks * 8 + tg * 2];
            a[mt][0] = p0.x; a[mt][1] = p1.x; a[mt][2] = p0.y; a[mt][3] = p1.y;
        }
        uint32_t b[8][2];
        const uint32_t* brow = &Wp[(ks * 4 + tg) * SWP + g * 16];
#pragma unroll
        for (int m = 0; m < 4; m++) {
            const uint4 bb = *(const uint4*)(brow + m * 4);
            b[2 * m][0]     = bb.x; b[2 * m][1]     = bb.y;
            b[2 * m + 1][0] = bb.z; b[2 * m + 1][1] = bb.w;
        }
#pragma unroll
        for (int mt = 0; mt < 2; mt++)
#pragma unroll
            for (int nt = 0; nt < 8; nt++)
                mma_tf32(acc[mt][nt], a[mt], b[nt]);
    }

    // Epilogue: norm-scale into smem, then coalesced red.v4.
    __syncthreads();
#pragma unroll
    for (int mt = 0; mt < 2; mt++) {
        const int lr0 = wrow + mt * 16 + g, lr1 = lr0 + 8;
        const float n0 = s_norm[lr0], n1 = s_norm[lr1];
#pragma unroll
        for (int nt = 0; nt < 8; nt++) {
            const int oc = nt * 8 + 2 * tg;
            *(float2*)&E[lr0 * ESTR + oc] =
                make_float2(acc[mt][nt][0] * n0, acc[mt][nt][1] * n0);
            *(float2*)&E[lr1 * ESTR + oc] =
                make_float2(acc[mt][nt][2] * n1, acc[mt][nt][3] * n1);
        }
    }
    __syncthreads();

    const int erow = tid >> 4, q4 = (tid & 15) * 4;
#pragma unroll
    for (int p = 0; p < 16; p++) {
        const int row = p * 8 + erow;
        const float4 v = *(const float4*)&E[row * ESTR + q4];
        float* o = out + (size_t)s_dst[row] * DD + q4;
        asm volatile("red.global.add.v4.f32 [%0], {%1, %2, %3, %4};"
                     :: "l"(o), "f"(v.x), "f"(v.y), "f"(v.z), "f"(v.w)
                     : "memory");
    }
}

// ---------------------------------------------------------------------------
extern "C" void kernel_launch(void* const* d_in, const int* in_sizes, int n_in,
                              void* d_out, int out_size) {
    const float* h    = (const float*)d_in[0];
    const float* W    = (const float*)d_in[1];
    const int*   src  = (const int*)d_in[2];
    const int*   dst  = (const int*)d_in[3];
    const int*   rel  = (const int*)d_in[4];
    const float* norm = (const float*)d_in[5];
    float*       out  = (float*)d_out;

    const int n_edges = in_sizes[2];   // 1600000

    void* p_cnt;
    cudaGetSymbolAddress(&p_cnt, g_binCount);
    cudaMemsetAsync(out,   0, (size_t)out_size * sizeof(float), 0);
    cudaMemsetAsync(p_cnt, 0, sizeof(int) * NR, 0);

    k_convert_hist<<<(NN * DD + 255) / 256, 256>>>(h, W, rel, n_edges);
    k_prefix<<<1, 32>>>();
    k_scatter<<<(n_edges + 511) / 512, 256>>>(src, dst, rel, norm, n_edges);

    const int smem_bytes = (WP_ROW + TILE * SA + TILE + TILE) * 4;
    static bool attr_set = false;
    if (!attr_set) {
        cudaFuncSetAttribute(rgcn_fused,
                             cudaFuncAttributeMaxDynamicSharedMemorySize,
                             smem_bytes);
        attr_set = true;
    }
    const int max_tiles = n_edges / TILE + NR + 1;
    rgcn_fused<<<max_tiles, 128, smem_bytes>>>(out);
}